// round 15
// baseline (speedup 1.0000x reference)
#include <cuda_runtime.h>
#include <cuda_bf16.h>
#include <cstdint>

// ---------------------------------------------------------------------------
// 3-layer GraphSAGE (mean aggregation), fp32-grade via bf16 hi/lo pairs.
//   activations stored packed: u32 = (bf16_hi << 16) | bf16_lo, value = hi+lo
//   aggregation: CSR segment-mean gather, uint4/lane, 8x unrolled (R11 shape)
//   GEMM: mma.sync m16n8k16 bf16, 3 products, cp.async 2-stage pipeline,
//         PRMT hi/lo extraction. Layer 0 split: x@W_r0 overlaps CSR+agg0.
// N = 100000, E = 1600000, dims 128 -> 256 -> 256 -> 256.
// ---------------------------------------------------------------------------

#define NN 100000
#define NE 1600000
#define CMAX 256

// ---------------- packed activation buffers --------------------------------
__device__ uint32_t g_xp  [(size_t)NN * 128];
__device__ uint32_t g_aggp[(size_t)NN * CMAX];
__device__ uint32_t g_h0p [(size_t)NN * CMAX];
__device__ uint32_t g_h1p [(size_t)NN * CMAX];
__device__ float    g_tmpf[(size_t)NN * CMAX];   // layer-0 partial (x @ W_r0)

// packed transposed weights [N=256, K] (K contiguous)
// offsets: l0:0(K=128) r0:32768  l1:65536 r1:131072 l2:196608 r2:262144
#define WBUF_TOTAL (2 * 128 * 256 + 4 * 256 * 256)
__device__ uint32_t g_Wp[WBUF_TOTAL];

// CSR build
#define SCAN_B 512
#define NB1 ((NN + SCAN_B - 1) / SCAN_B)
__device__ int g_cnt[NN];
__device__ int g_pos[NN];
__device__ int g_rowptr[NN];
__device__ int g_srcs[NE];
__device__ int g_scan[NN];
__device__ int g_part[NB1];
__device__ int g_partscan[NB1];

// ---------------------------------------------------------------------------
// helpers
// ---------------------------------------------------------------------------
__device__ __forceinline__ uint32_t pack_split(float v) {
    __nv_bfloat16 h = __float2bfloat16_rn(v);
    float r = v - __bfloat162float(h);
    __nv_bfloat16 l = __float2bfloat16_rn(r);
    return ((uint32_t)__bfloat16_as_ushort(h) << 16) | (uint32_t)__bfloat16_as_ushort(l);
}
__device__ __forceinline__ float unpack_val(uint32_t p) {
    return __uint_as_float(p & 0xFFFF0000u) + __uint_as_float(p << 16);
}
__device__ __forceinline__ void cpa16(uint32_t saddr, const void* g, int sz) {
    asm volatile("cp.async.ca.shared.global [%0], [%1], 16, %2;"
                 :: "r"(saddr), "l"(g), "r"(sz) : "memory");
}
__device__ __forceinline__ uint32_t smem_u32p(const void* p) {
    uint32_t a;
    asm("{ .reg .u64 t; cvta.to.shared.u64 t, %1; cvt.u32.u64 %0, t; }" : "=r"(a) : "l"(p));
    return a;
}
__device__ __forceinline__ void mma_bf16(float* c, const uint32_t* a, const uint32_t* b) {
    asm volatile(
        "mma.sync.aligned.m16n8k16.row.col.f32.bf16.bf16.f32 "
        "{%0,%1,%2,%3}, {%4,%5,%6,%7}, {%8,%9}, {%0,%1,%2,%3};"
        : "+f"(c[0]), "+f"(c[1]), "+f"(c[2]), "+f"(c[3])
        : "r"(a[0]), "r"(a[1]), "r"(a[2]), "r"(a[3]), "r"(b[0]), "r"(b[1]));
}

// ---------------------------------------------------------------------------
// CSR build kernels
// ---------------------------------------------------------------------------
__global__ void k_zero_cnt() {
    int i = blockIdx.x * blockDim.x + threadIdx.x;
    if (i < NN) { g_cnt[i] = 0; g_pos[i] = 0; }
}
__global__ void k_hist(const int* __restrict__ dst) {
    int i = blockIdx.x * blockDim.x + threadIdx.x;
    if (i < NE) atomicAdd(&g_cnt[dst[i]], 1);
}
__global__ void k_scan1() {
    __shared__ int s[SCAN_B];
    int t = threadIdx.x;
    int idx = blockIdx.x * SCAN_B + t;
    int v = (idx < NN) ? g_cnt[idx] : 0;
    s[t] = v;
    __syncthreads();
#pragma unroll
    for (int off = 1; off < SCAN_B; off <<= 1) {
        int tmp = (t >= off) ? s[t - off] : 0;
        __syncthreads();
        s[t] += tmp;
        __syncthreads();
    }
    if (idx < NN) g_scan[idx] = s[t];
    if (t == SCAN_B - 1) g_part[blockIdx.x] = s[t];
}
__global__ void k_scan2() {
    __shared__ int s[256];
    int t = threadIdx.x;
    int v = (t < NB1) ? g_part[t] : 0;
    s[t] = v;
    __syncthreads();
#pragma unroll
    for (int off = 1; off < 256; off <<= 1) {
        int tmp = (t >= off) ? s[t - off] : 0;
        __syncthreads();
        s[t] += tmp;
        __syncthreads();
    }
    if (t < NB1) g_partscan[t] = s[t];
}
__global__ void k_scan3() {
    int idx = blockIdx.x * blockDim.x + threadIdx.x;
    if (idx < NN) {
        int b = idx / SCAN_B;
        int boff = (b > 0) ? g_partscan[b - 1] : 0;
        g_rowptr[idx] = g_scan[idx] - g_cnt[idx] + boff;
    }
}
__global__ void k_place(const int* __restrict__ src, const int* __restrict__ dst) {
    int i = blockIdx.x * blockDim.x + threadIdx.x;
    if (i < NE) {
        int d = dst[i];
        int pos = g_rowptr[d] + atomicAdd(&g_pos[d], 1);
        g_srcs[pos] = src[i];
    }
}

// ---------------------------------------------------------------------------
// prep: pack x; pack+transpose all 6 weights in ONE kernel
// ---------------------------------------------------------------------------
__global__ void k_prep_x(const float* __restrict__ x) {
    int i = blockIdx.x * blockDim.x + threadIdx.x;
    if (i < NN * 128) g_xp[i] = pack_split(x[i]);
}
__global__ void k_prep_w_all(const float* __restrict__ Wl0, const float* __restrict__ Wr0,
                             const float* __restrict__ Wl1, const float* __restrict__ Wr1,
                             const float* __restrict__ Wl2, const float* __restrict__ Wr2) {
    int i = blockIdx.x * blockDim.x + threadIdx.x;
    if (i >= WBUF_TOTAL) return;
    const float* W;
    int base, K, li;
    if (i < 65536) {
        K = 128;
        if (i < 32768) { W = Wl0; base = 0; li = i; }
        else           { W = Wr0; base = 32768; li = i - 32768; }
    } else {
        K = 256;
        int j = i - 65536;
        int seg = j >> 16;
        li = j & 65535;
        base = 65536 + (seg << 16);
        W = (seg == 0) ? Wl1 : (seg == 1) ? Wr1 : (seg == 2) ? Wl2 : Wr2;
    }
    int k = li >> 8;
    int n = li & 255;
    g_Wp[base + n * K + k] = pack_split(W[li]);
}

// ---------------------------------------------------------------------------
// aggregation: segment-mean gather over packed values. one warp per
// (node, 128-ch chunk); lanes hold 4 channels each (uint4). 8x unrolled.
// ---------------------------------------------------------------------------
__device__ __forceinline__ void acc_packed(float4& a, uint4 v) {
    a.x += unpack_val(v.x);
    a.y += unpack_val(v.y);
    a.z += unpack_val(v.z);
    a.w += unpack_val(v.w);
}

template <int CHUNKS>
__global__ void k_aggregate(int xsel) {
    const uint32_t* x = (xsel == 0) ? g_xp : (xsel == 1 ? g_h0p : g_h1p);
    const int CV = CHUNKS * 32;   // uint4 per row
    int gw = (blockIdx.x * blockDim.x + threadIdx.x) >> 5;
    int lane = threadIdx.x & 31;
    int node = gw / CHUNKS;
    int chunk = gw - node * CHUNKS;
    if (node >= NN) return;

    int beg = g_rowptr[node];
    int len = g_cnt[node];
    int end = beg + len;
    size_t coff = (size_t)chunk * 32 + lane;
    const uint4* xv = reinterpret_cast<const uint4*>(x);
    float4 acc = make_float4(0.f, 0.f, 0.f, 0.f);

    int j = beg;
    for (; j + 8 <= end; j += 8) {
        int s0 = __ldg(&g_srcs[j + 0]);
        int s1 = __ldg(&g_srcs[j + 1]);
        int s2 = __ldg(&g_srcs[j + 2]);
        int s3 = __ldg(&g_srcs[j + 3]);
        int s4 = __ldg(&g_srcs[j + 4]);
        int s5 = __ldg(&g_srcs[j + 5]);
        int s6 = __ldg(&g_srcs[j + 6]);
        int s7 = __ldg(&g_srcs[j + 7]);
        uint4 v0 = xv[(size_t)s0 * CV + coff];
        uint4 v1 = xv[(size_t)s1 * CV + coff];
        uint4 v2 = xv[(size_t)s2 * CV + coff];
        uint4 v3 = xv[(size_t)s3 * CV + coff];
        uint4 v4 = xv[(size_t)s4 * CV + coff];
        uint4 v5 = xv[(size_t)s5 * CV + coff];
        uint4 v6 = xv[(size_t)s6 * CV + coff];
        uint4 v7 = xv[(size_t)s7 * CV + coff];
        acc_packed(acc, v0); acc_packed(acc, v1);
        acc_packed(acc, v2); acc_packed(acc, v3);
        acc_packed(acc, v4); acc_packed(acc, v5);
        acc_packed(acc, v6); acc_packed(acc, v7);
    }
    for (; j + 2 <= end; j += 2) {
        int s0 = __ldg(&g_srcs[j + 0]);
        int s1 = __ldg(&g_srcs[j + 1]);
        uint4 v0 = xv[(size_t)s0 * CV + coff];
        uint4 v1 = xv[(size_t)s1 * CV + coff];
        acc_packed(acc, v0); acc_packed(acc, v1);
    }
    for (; j < end; ++j) {
        int s = __ldg(&g_srcs[j]);
        acc_packed(acc, xv[(size_t)s * CV + coff]);
    }
    float inv = 1.0f / fmaxf((float)len, 1.0f);
    uint4 o;
    o.x = pack_split(acc.x * inv);
    o.y = pack_split(acc.y * inv);
    o.z = pack_split(acc.z * inv);
    o.w = pack_split(acc.w * inv);
    reinterpret_cast<uint4*>(g_aggp)[(size_t)node * CV + coff] = o;
}

// ---------------------------------------------------------------------------
// GEMM: C = [do_l: agg@W_l] + [do_r: A2@W_r] + [add_tmp: g_tmpf] + bias (+relu)
//   packed smem, cp.async 2-stage pipeline, PRMT hi/lo extraction,
//   3 mma products per tile. csel: 0=ext fp32, 1=h0p, 2=h1p, 3=tmpf(fp32)
// ---------------------------------------------------------------------------
#define BM 128
#define BN 128
#define S40 40                      // u32 stride per smem row (32 data + 8 pad)
#define ASZ (128 * S40)             // 5120 u32 per stage array
#define STGU (2 * ASZ)              // A + B per stage (u32)
#define SMEM_BYTES (2 * STGU * 4)   // 81920

__global__ __launch_bounds__(256, 2)
void k_gemm_mma(int a2sel, int woff_l, int woff_r,
                const float* __restrict__ bias,
                float* __restrict__ Cext, int csel,
                int K, int relu, int do_l, int do_r, int add_tmp) {
    extern __shared__ uint32_t smem[];
    const uint32_t sb = smem_u32p(smem);

    const uint32_t* A2 = (a2sel == 0) ? g_xp : (a2sel == 1 ? g_h0p : g_h1p);
    const int tid  = threadIdx.x;
    const int wid  = tid >> 5;
    const int lane = tid & 31;
    const int wm   = wid & 3;
    const int wn   = wid >> 2;
    const int bm   = blockIdx.x * BM;
    const int bn   = blockIdx.y * BN;
    const int r4   = lane >> 2;
    const int c2   = (lane & 3) * 2;

    const int KCH = K / 32;
    const int NCH = (do_l + do_r) * KCH;

    float acc[2][8][4];
#pragma unroll
    for (int mt = 0; mt < 2; mt++)
#pragma unroll
        for (int nt = 0; nt < 8; nt++)
#pragma unroll
            for (int q = 0; q < 4; q++) acc[mt][nt][q] = 0.0f;

    auto issue = [&](int c) {
        int part = (c >= KCH) ? 1 : (do_l ? 0 : 1);
        int kc = (c >= KCH) ? (c - KCH) : c;
        int k0 = kc * 32;
        const uint32_t* Abase = part ? A2 : g_aggp;
        int woff = part ? woff_r : woff_l;
        int buf = c & 1;
        uint32_t sA = sb + (buf * STGU) * 4;
        uint32_t sB = sA + ASZ * 4;
#pragma unroll
        for (int i = 0; i < 4; ++i) {
            int f = tid + 256 * i;
            int row = f >> 3, c4 = f & 7;
            int rg = bm + row;
            const uint32_t* src = Abase + (size_t)rg * K + k0 + c4 * 4;
            cpa16(sA + (row * S40 + c4 * 4) * 4, src, (rg < NN) ? 16 : 0);
        }
#pragma unroll
        for (int i = 0; i < 4; ++i) {
            int f = tid + 256 * i;
            int n = f >> 3, c4 = f & 7;
            const uint32_t* src = g_Wp + woff + (size_t)(bn + n) * K + k0 + c4 * 4;
            cpa16(sB + (n * S40 + c4 * 4) * 4, src, 16);
        }
        asm volatile("cp.async.commit_group;" ::: "memory");
    };

    issue(0);
    if (NCH > 1) issue(1);

#pragma unroll 1
    for (int c = 0; c < NCH; ++c) {
        if (c + 1 < NCH)
            asm volatile("cp.async.wait_group 1;" ::: "memory");
        else
            asm volatile("cp.async.wait_group 0;" ::: "memory");
        __syncthreads();

        const uint32_t* sA = smem + (c & 1) * STGU;
        const uint32_t* sB = sA + ASZ;

#pragma unroll
        for (int kk = 0; kk < 32; kk += 16) {
            uint32_t ah[2][4], al[2][4];
#pragma unroll
            for (int mt = 0; mt < 2; ++mt) {
                int rb = (wm * 32 + mt * 16 + r4) * S40 + kk + c2;
                uint2 q0 = *reinterpret_cast<const uint2*>(&sA[rb]);
                uint2 q1 = *reinterpret_cast<const uint2*>(&sA[rb + 8 * S40]);
                uint2 q2 = *reinterpret_cast<const uint2*>(&sA[rb + 8]);
                uint2 q3 = *reinterpret_cast<const uint2*>(&sA[rb + 8 * S40 + 8]);
                ah[mt][0] = __byte_perm(q0.x, q0.y, 0x7632);
                al[mt][0] = __byte_perm(q0.x, q0.y, 0x5410);
                ah[mt][1] = __byte_perm(q1.x, q1.y, 0x7632);
                al[mt][1] = __byte_perm(q1.x, q1.y, 0x5410);
                ah[mt][2] = __byte_perm(q2.x, q2.y, 0x7632);
                al[mt][2] = __byte_perm(q2.x, q2.y, 0x5410);
                ah[mt][3] = __byte_perm(q3.x, q3.y, 0x7632);
                al[mt][3] = __byte_perm(q3.x, q3.y, 0x5410);
            }
#pragma unroll
            for (int nt = 0; nt < 8; ++nt) {
                int nb = (wn * 64 + nt * 8 + r4) * S40 + kk + c2;
                uint2 q0 = *reinterpret_cast<const uint2*>(&sB[nb]);
                uint2 q1 = *reinterpret_cast<const uint2*>(&sB[nb + 8]);
                uint32_t bh[2], bl[2];
                bh[0] = __byte_perm(q0.x, q0.y, 0x7632);
                bl[0] = __byte_perm(q0.x, q0.y, 0x5410);
                bh[1] = __byte_perm(q1.x, q1.y, 0x7632);
                bl[1] = __byte_perm(q1.x, q1.y, 0x5410);
#pragma unroll
                for (int mt = 0; mt < 2; ++mt) {
                    mma_bf16(acc[mt][nt], ah[mt], bh);
                    mma_bf16(acc[mt][nt], al[mt], bh);
                    mma_bf16(acc[mt][nt], ah[mt], bl);
                }
            }
        }
        __syncthreads();
        if (c + 2 < NCH) issue(c + 2);
    }

    // ---- epilogue ----
    uint32_t* Cp = (csel == 1) ? g_h0p : g_h1p;
#pragma unroll
    for (int nt = 0; nt < 8; ++nt) {
        int col = bn + wn * 64 + nt * 8 + c2;
        float2 bv = make_float2(0.f, 0.f);
        if (bias) bv = *reinterpret_cast<const float2*>(bias + col);
#pragma unroll
        for (int mt = 0; mt < 2; ++mt) {
            int row0 = bm + wm * 32 + mt * 16 + r4;
            float2 o0, o1;
            o0.x = acc[mt][nt][0] + bv.x;
            o0.y = acc[mt][nt][1] + bv.y;
            o1.x = acc[mt][nt][2] + bv.x;
            o1.y = acc[mt][nt][3] + bv.y;
            if (add_tmp) {
                if (row0 < NN) {
                    float2 t = *reinterpret_cast<const float2*>(g_tmpf + (size_t)row0 * 256 + col);
                    o0.x += t.x; o0.y += t.y;
                }
                if (row0 + 8 < NN) {
                    float2 t = *reinterpret_cast<const float2*>(g_tmpf + (size_t)(row0 + 8) * 256 + col);
                    o1.x += t.x; o1.y += t.y;
                }
            }
            if (relu) {
                o0.x = fmaxf(o0.x, 0.f); o0.y = fmaxf(o0.y, 0.f);
                o1.x = fmaxf(o1.x, 0.f); o1.y = fmaxf(o1.y, 0.f);
            }
            if (csel == 0 || csel == 3) {
                float* dstp = (csel == 0) ? Cext : g_tmpf;
                if (row0 < NN)
                    *reinterpret_cast<float2*>(dstp + (size_t)row0 * 256 + col) = o0;
                if (row0 + 8 < NN)
                    *reinterpret_cast<float2*>(dstp + (size_t)(row0 + 8) * 256 + col) = o1;
            } else {
                if (row0 < NN) {
                    uint2 p = make_uint2(pack_split(o0.x), pack_split(o0.y));
                    *reinterpret_cast<uint2*>(Cp + (size_t)row0 * 256 + col) = p;
                }
                if (row0 + 8 < NN) {
                    uint2 p = make_uint2(pack_split(o1.x), pack_split(o1.y));
                    *reinterpret_cast<uint2*>(Cp + (size_t)(row0 + 8) * 256 + col) = p;
                }
            }
        }
    }
}

// ---------------------------------------------------------------------------
// launch:
//   stream B: CSR build -> agg0
//   stream A: prep_x, prep_w, gemm_r0 (x@W_r0 -> tmp, overlaps CSR+agg0),
//             [wait agg0] gemm_l0 (agg@W_l0 + tmp + b, relu) -> h0,
//             then fused layers 1, 2 (R11 schedule).
// ---------------------------------------------------------------------------
extern "C" void kernel_launch(void* const* d_in, const int* in_sizes, int n_in,
                              void* d_out, int out_size) {
    const float* x    = (const float*)d_in[0];
    const float* W_l0 = (const float*)d_in[1];
    const float* b_l0 = (const float*)d_in[2];
    const float* W_r0 = (const float*)d_in[3];
    const float* W_l1 = (const float*)d_in[4];
    const float* b_l1 = (const float*)d_in[5];
    const float* W_r1 = (const float*)d_in[6];
    const float* W_l2 = (const float*)d_in[7];
    const float* b_l2 = (const float*)d_in[8];
    const float* W_r2 = (const float*)d_in[9];
    const int*   src  = (const int*)d_in[10];
    const int*   dst  = (const int*)d_in[11];
    float*       out  = (float*)d_out;

    const int T = 256;
    dim3 gg((NN + BM - 1) / BM, 256 / BN);

    static cudaStream_t sB = nullptr;
    static cudaEvent_t evFork, evPrepX, evAgg0;
    if (!sB) {
        cudaStreamCreateWithFlags(&sB, cudaStreamNonBlocking);
        cudaEventCreateWithFlags(&evFork, cudaEventDisableTiming);
        cudaEventCreateWithFlags(&evPrepX, cudaEventDisableTiming);
        cudaEventCreateWithFlags(&evAgg0, cudaEventDisableTiming);
        cudaFuncSetAttribute(k_gemm_mma, cudaFuncAttributeMaxDynamicSharedMemorySize,
                             SMEM_BYTES);
    }

    // ---- fork: CSR build on stream B ----
    cudaEventRecord(evFork, 0);
    cudaStreamWaitEvent(sB, evFork, 0);
    k_zero_cnt<<<(NN + T - 1) / T, T, 0, sB>>>();
    k_hist<<<(NE + T - 1) / T, T, 0, sB>>>(dst);
    k_scan1<<<NB1, SCAN_B, 0, sB>>>();
    k_scan2<<<1, 256, 0, sB>>>();
    k_scan3<<<(NN + T - 1) / T, T, 0, sB>>>();
    k_place<<<(NE + T - 1) / T, T, 0, sB>>>(src, dst);

    // ---- prep on stream A (overlaps CSR) ----
    k_prep_x<<<(NN * 128 + T - 1) / T, T>>>(x);
    cudaEventRecord(evPrepX, 0);
    k_prep_w_all<<<(WBUF_TOTAL + T - 1) / T, T>>>(W_l0, W_r0, W_l1, W_r1, W_l2, W_r2);

    // ---- stream B: agg0 (needs CSR + prep_x) ----
    cudaStreamWaitEvent(sB, evPrepX, 0);
    k_aggregate<1><<<(NN * 32 + T - 1) / T, T, 0, sB>>>(0);
    cudaEventRecord(evAgg0, sB);

    // ---- stream A: gemm_r0 = x @ W_r0 -> tmp (overlaps CSR + agg0) ----
    k_gemm_mma<<<gg, T, SMEM_BYTES>>>(0, 0, 32768, nullptr, nullptr, 3, 128, 0,
                                      /*do_l=*/0, /*do_r=*/1, /*add_tmp=*/0);

    // ---- join; gemm_l0 = agg @ W_l0 + tmp + b (relu) -> h0 ----
    cudaStreamWaitEvent(0, evAgg0, 0);
    k_gemm_mma<<<gg, T, SMEM_BYTES>>>(0, 0, 32768, b_l0, nullptr, 1, 128, 1,
                                      /*do_l=*/1, /*do_r=*/0, /*add_tmp=*/1);

    // ---- layer 1 (K = 256, fused) ----
    k_aggregate<2><<<(NN * 2 * 32 + T - 1) / T, T>>>(1);
    k_gemm_mma<<<gg, T, SMEM_BYTES>>>(1, 65536, 131072, b_l1, nullptr, 2, 256, 1,
                                      1, 1, 0);

    // ---- layer 2 (K = 256, fused, no relu, write d_out) ----
    k_aggregate<2><<<(NN * 2 * 32 + T - 1) / T, T>>>(2);
    k_gemm_mma<<<gg, T, SMEM_BYTES>>>(2, 196608, 262144, b_l2, out, 0, 256, 0,
                                      1, 1, 0);
}

// round 16
// speedup vs baseline: 1.0585x; 1.0585x over previous
#include <cuda_runtime.h>
#include <cuda_bf16.h>
#include <cstdint>

// ---------------------------------------------------------------------------
// 3-layer GraphSAGE (mean aggregation), fp32-grade via bf16 hi/lo pairs.
//   activations stored packed: u32 = (bf16_hi << 16) | bf16_lo, value = hi+lo
//   aggregation: CSR segment-mean gather, uint4/lane, 8x unrolled (R11 shape)
//   GEMM: mma.sync m16n8k16 bf16, 3 products (AhBh + AlBh + AhBl),
//         cp.async double-buffered pipeline, PRMT hi/lo extraction.
//   CSR build (vectorized hist/place) overlapped with prep on a 2nd stream.
// N = 100000, E = 1600000, dims 128 -> 256 -> 256 -> 256.
// ---------------------------------------------------------------------------

#define NN 100000
#define NE 1600000
#define CMAX 256

// ---------------- packed activation buffers --------------------------------
__device__ uint32_t g_xp  [(size_t)NN * 128];
__device__ uint32_t g_aggp[(size_t)NN * CMAX];
__device__ uint32_t g_h0p [(size_t)NN * CMAX];
__device__ uint32_t g_h1p [(size_t)NN * CMAX];

// packed transposed weights [N=256, K] (K contiguous)
// offsets: l0:0(K=128) r0:32768  l1:65536 r1:131072 l2:196608 r2:262144
#define WBUF_TOTAL (2 * 128 * 256 + 4 * 256 * 256)
__device__ uint32_t g_Wp[WBUF_TOTAL];

// CSR build
#define SCAN_B 512
#define NB1 ((NN + SCAN_B - 1) / SCAN_B)
__device__ int g_cnt[NN];
__device__ int g_pos[NN];
__device__ int g_rowptr[NN];
__device__ int g_srcs[NE];
__device__ int g_scan[NN];
__device__ int g_part[NB1];
__device__ int g_partscan[NB1];

// ---------------------------------------------------------------------------
// helpers
// ---------------------------------------------------------------------------
__device__ __forceinline__ uint32_t pack_split(float v) {
    __nv_bfloat16 h = __float2bfloat16_rn(v);
    float r = v - __bfloat162float(h);
    __nv_bfloat16 l = __float2bfloat16_rn(r);
    return ((uint32_t)__bfloat16_as_ushort(h) << 16) | (uint32_t)__bfloat16_as_ushort(l);
}
__device__ __forceinline__ float unpack_val(uint32_t p) {
    return __uint_as_float(p & 0xFFFF0000u) + __uint_as_float(p << 16);
}
__device__ __forceinline__ void cpa16(uint32_t saddr, const void* g, int sz) {
    asm volatile("cp.async.ca.shared.global [%0], [%1], 16, %2;"
                 :: "r"(saddr), "l"(g), "r"(sz) : "memory");
}
__device__ __forceinline__ uint32_t smem_u32p(const void* p) {
    uint32_t a;
    asm("{ .reg .u64 t; cvta.to.shared.u64 t, %1; cvt.u32.u64 %0, t; }" : "=r"(a) : "l"(p));
    return a;
}
__device__ __forceinline__ void mma_bf16(float* c, const uint32_t* a, const uint32_t* b) {
    asm volatile(
        "mma.sync.aligned.m16n8k16.row.col.f32.bf16.bf16.f32 "
        "{%0,%1,%2,%3}, {%4,%5,%6,%7}, {%8,%9}, {%0,%1,%2,%3};"
        : "+f"(c[0]), "+f"(c[1]), "+f"(c[2]), "+f"(c[3])
        : "r"(a[0]), "r"(a[1]), "r"(a[2]), "r"(a[3]), "r"(b[0]), "r"(b[1]));
}

// ---------------------------------------------------------------------------
// CSR build kernels (hist/place vectorized: 4 edges per thread)
// ---------------------------------------------------------------------------
__global__ void k_zero_cnt() {
    int i = blockIdx.x * blockDim.x + threadIdx.x;
    if (i < NN) { g_cnt[i] = 0; g_pos[i] = 0; }
}
__global__ void k_hist(const int* __restrict__ dst) {
    int i = blockIdx.x * blockDim.x + threadIdx.x;
    if (i < NE / 4) {
        int4 d = reinterpret_cast<const int4*>(dst)[i];
        atomicAdd(&g_cnt[d.x], 1);
        atomicAdd(&g_cnt[d.y], 1);
        atomicAdd(&g_cnt[d.z], 1);
        atomicAdd(&g_cnt[d.w], 1);
    }
}
__global__ void k_scan1() {
    __shared__ int s[SCAN_B];
    int t = threadIdx.x;
    int idx = blockIdx.x * SCAN_B + t;
    int v = (idx < NN) ? g_cnt[idx] : 0;
    s[t] = v;
    __syncthreads();
#pragma unroll
    for (int off = 1; off < SCAN_B; off <<= 1) {
        int tmp = (t >= off) ? s[t - off] : 0;
        __syncthreads();
        s[t] += tmp;
        __syncthreads();
    }
    if (idx < NN) g_scan[idx] = s[t];
    if (t == SCAN_B - 1) g_part[blockIdx.x] = s[t];
}
__global__ void k_scan2() {
    __shared__ int s[256];
    int t = threadIdx.x;
    int v = (t < NB1) ? g_part[t] : 0;
    s[t] = v;
    __syncthreads();
#pragma unroll
    for (int off = 1; off < 256; off <<= 1) {
        int tmp = (t >= off) ? s[t - off] : 0;
        __syncthreads();
        s[t] += tmp;
        __syncthreads();
    }
    if (t < NB1) g_partscan[t] = s[t];
}
__global__ void k_scan3() {
    int idx = blockIdx.x * blockDim.x + threadIdx.x;
    if (idx < NN) {
        int b = idx / SCAN_B;
        int boff = (b > 0) ? g_partscan[b - 1] : 0;
        g_rowptr[idx] = g_scan[idx] - g_cnt[idx] + boff;
    }
}
__global__ void k_place(const int* __restrict__ src, const int* __restrict__ dst) {
    int i = blockIdx.x * blockDim.x + threadIdx.x;
    if (i < NE / 4) {
        int4 d = reinterpret_cast<const int4*>(dst)[i];
        int4 s = reinterpret_cast<const int4*>(src)[i];
        g_srcs[g_rowptr[d.x] + atomicAdd(&g_pos[d.x], 1)] = s.x;
        g_srcs[g_rowptr[d.y] + atomicAdd(&g_pos[d.y], 1)] = s.y;
        g_srcs[g_rowptr[d.z] + atomicAdd(&g_pos[d.z], 1)] = s.z;
        g_srcs[g_rowptr[d.w] + atomicAdd(&g_pos[d.w], 1)] = s.w;
    }
}

// ---------------------------------------------------------------------------
// prep: pack x; pack+transpose all 6 weights in ONE kernel
// ---------------------------------------------------------------------------
__global__ void k_prep_x(const float* __restrict__ x) {
    int i = blockIdx.x * blockDim.x + threadIdx.x;
    if (i < NN * 128) g_xp[i] = pack_split(x[i]);
}
__global__ void k_prep_w_all(const float* __restrict__ Wl0, const float* __restrict__ Wr0,
                             const float* __restrict__ Wl1, const float* __restrict__ Wr1,
                             const float* __restrict__ Wl2, const float* __restrict__ Wr2) {
    int i = blockIdx.x * blockDim.x + threadIdx.x;
    if (i >= WBUF_TOTAL) return;
    const float* W;
    int base, K, li;
    if (i < 65536) {
        K = 128;
        if (i < 32768) { W = Wl0; base = 0; li = i; }
        else           { W = Wr0; base = 32768; li = i - 32768; }
    } else {
        K = 256;
        int j = i - 65536;
        int seg = j >> 16;
        li = j & 65535;
        base = 65536 + (seg << 16);
        W = (seg == 0) ? Wl1 : (seg == 1) ? Wr1 : (seg == 2) ? Wl2 : Wr2;
    }
    int k = li >> 8;
    int n = li & 255;
    g_Wp[base + n * K + k] = pack_split(W[li]);
}

// ---------------------------------------------------------------------------
// aggregation: segment-mean gather over packed values. one warp per
// (node, 128-ch chunk); lanes hold 4 channels each (uint4). 8x unrolled.
// ---------------------------------------------------------------------------
__device__ __forceinline__ void acc_packed(float4& a, uint4 v) {
    a.x += unpack_val(v.x);
    a.y += unpack_val(v.y);
    a.z += unpack_val(v.z);
    a.w += unpack_val(v.w);
}

template <int CHUNKS>
__global__ void k_aggregate(int xsel) {
    const uint32_t* x = (xsel == 0) ? g_xp : (xsel == 1 ? g_h0p : g_h1p);
    const int CV = CHUNKS * 32;   // uint4 per row
    int gw = (blockIdx.x * blockDim.x + threadIdx.x) >> 5;
    int lane = threadIdx.x & 31;
    int node = gw / CHUNKS;
    int chunk = gw - node * CHUNKS;
    if (node >= NN) return;

    int beg = g_rowptr[node];
    int len = g_cnt[node];
    int end = beg + len;
    size_t coff = (size_t)chunk * 32 + lane;
    const uint4* xv = reinterpret_cast<const uint4*>(x);
    float4 acc = make_float4(0.f, 0.f, 0.f, 0.f);

    int j = beg;
    for (; j + 8 <= end; j += 8) {
        int s0 = __ldg(&g_srcs[j + 0]);
        int s1 = __ldg(&g_srcs[j + 1]);
        int s2 = __ldg(&g_srcs[j + 2]);
        int s3 = __ldg(&g_srcs[j + 3]);
        int s4 = __ldg(&g_srcs[j + 4]);
        int s5 = __ldg(&g_srcs[j + 5]);
        int s6 = __ldg(&g_srcs[j + 6]);
        int s7 = __ldg(&g_srcs[j + 7]);
        uint4 v0 = xv[(size_t)s0 * CV + coff];
        uint4 v1 = xv[(size_t)s1 * CV + coff];
        uint4 v2 = xv[(size_t)s2 * CV + coff];
        uint4 v3 = xv[(size_t)s3 * CV + coff];
        uint4 v4 = xv[(size_t)s4 * CV + coff];
        uint4 v5 = xv[(size_t)s5 * CV + coff];
        uint4 v6 = xv[(size_t)s6 * CV + coff];
        uint4 v7 = xv[(size_t)s7 * CV + coff];
        acc_packed(acc, v0); acc_packed(acc, v1);
        acc_packed(acc, v2); acc_packed(acc, v3);
        acc_packed(acc, v4); acc_packed(acc, v5);
        acc_packed(acc, v6); acc_packed(acc, v7);
    }
    for (; j + 2 <= end; j += 2) {
        int s0 = __ldg(&g_srcs[j + 0]);
        int s1 = __ldg(&g_srcs[j + 1]);
        uint4 v0 = xv[(size_t)s0 * CV + coff];
        uint4 v1 = xv[(size_t)s1 * CV + coff];
        acc_packed(acc, v0); acc_packed(acc, v1);
    }
    for (; j < end; ++j) {
        int s = __ldg(&g_srcs[j]);
        acc_packed(acc, xv[(size_t)s * CV + coff]);
    }
    float inv = 1.0f / fmaxf((float)len, 1.0f);
    uint4 o;
    o.x = pack_split(acc.x * inv);
    o.y = pack_split(acc.y * inv);
    o.z = pack_split(acc.z * inv);
    o.w = pack_split(acc.w * inv);
    reinterpret_cast<uint4*>(g_aggp)[(size_t)node * CV + coff] = o;
}

// ---------------------------------------------------------------------------
// fused dual-GEMM: C = agg@W_l + A2@W_r + bias (+relu)
//   packed smem, cp.async 2-stage pipeline, PRMT hi/lo extraction,
//   3 mma products per tile.  (R11 structure — measured optimum)
// ---------------------------------------------------------------------------
#define BM 128
#define BN 128
#define S40 40                      // u32 stride per smem row (32 data + 8 pad)
#define ASZ (128 * S40)             // 5120 u32 per stage array
#define STGU (2 * ASZ)              // A + B per stage (u32)
#define SMEM_BYTES (2 * STGU * 4)   // 81920

__global__ __launch_bounds__(256, 2)
void k_gemm_mma(int a2sel, int woff_l, int woff_r,
                const float* __restrict__ bias,
                float* __restrict__ Cext, int csel,
                int K, int relu) {
    extern __shared__ uint32_t smem[];
    const uint32_t sb = smem_u32p(smem);

    const uint32_t* A2 = (a2sel == 0) ? g_xp : (a2sel == 1 ? g_h0p : g_h1p);
    const int tid  = threadIdx.x;
    const int wid  = tid >> 5;
    const int lane = tid & 31;
    const int wm   = wid & 3;
    const int wn   = wid >> 2;
    const int bm   = blockIdx.x * BM;
    const int bn   = blockIdx.y * BN;
    const int r4   = lane >> 2;
    const int c2   = (lane & 3) * 2;

    const int KCH = K / 32;
    const int NCH = 2 * KCH;

    float acc[2][8][4];
#pragma unroll
    for (int mt = 0; mt < 2; mt++)
#pragma unroll
        for (int nt = 0; nt < 8; nt++)
#pragma unroll
            for (int q = 0; q < 4; q++) acc[mt][nt][q] = 0.0f;

    auto issue = [&](int c) {
        int part = (c >= KCH) ? 1 : 0;
        int k0 = (c - part * KCH) * 32;
        const uint32_t* Abase = part ? A2 : g_aggp;
        int woff = part ? woff_r : woff_l;
        int buf = c & 1;
        uint32_t sA = sb + (buf * STGU) * 4;
        uint32_t sB = sA + ASZ * 4;
#pragma unroll
        for (int i = 0; i < 4; ++i) {
            int f = tid + 256 * i;
            int row = f >> 3, c4 = f & 7;
            int rg = bm + row;
            const uint32_t* src = Abase + (size_t)rg * K + k0 + c4 * 4;
            cpa16(sA + (row * S40 + c4 * 4) * 4, src, (rg < NN) ? 16 : 0);
        }
#pragma unroll
        for (int i = 0; i < 4; ++i) {
            int f = tid + 256 * i;
            int n = f >> 3, c4 = f & 7;
            const uint32_t* src = g_Wp + woff + (size_t)(bn + n) * K + k0 + c4 * 4;
            cpa16(sB + (n * S40 + c4 * 4) * 4, src, 16);
        }
        asm volatile("cp.async.commit_group;" ::: "memory");
    };

    issue(0);
    if (NCH > 1) issue(1);

#pragma unroll 1
    for (int c = 0; c < NCH; ++c) {
        if (c + 1 < NCH)
            asm volatile("cp.async.wait_group 1;" ::: "memory");
        else
            asm volatile("cp.async.wait_group 0;" ::: "memory");
        __syncthreads();

        const uint32_t* sA = smem + (c & 1) * STGU;
        const uint32_t* sB = sA + ASZ;

#pragma unroll
        for (int kk = 0; kk < 32; kk += 16) {
            uint32_t ah[2][4], al[2][4];
#pragma unroll
            for (int mt = 0; mt < 2; ++mt) {
                int rb = (wm * 32 + mt * 16 + r4) * S40 + kk + c2;
                uint2 q0 = *reinterpret_cast<const uint2*>(&sA[rb]);
                uint2 q1 = *reinterpret_cast<const uint2*>(&sA[rb + 8 * S40]);
                uint2 q2 = *reinterpret_cast<const uint2*>(&sA[rb + 8]);
                uint2 q3 = *reinterpret_cast<const uint2*>(&sA[rb + 8 * S40 + 8]);
                ah[mt][0] = __byte_perm(q0.x, q0.y, 0x7632);
                al[mt][0] = __byte_perm(q0.x, q0.y, 0x5410);
                ah[mt][1] = __byte_perm(q1.x, q1.y, 0x7632);
                al[mt][1] = __byte_perm(q1.x, q1.y, 0x5410);
                ah[mt][2] = __byte_perm(q2.x, q2.y, 0x7632);
                al[mt][2] = __byte_perm(q2.x, q2.y, 0x5410);
                ah[mt][3] = __byte_perm(q3.x, q3.y, 0x7632);
                al[mt][3] = __byte_perm(q3.x, q3.y, 0x5410);
            }
#pragma unroll
            for (int nt = 0; nt < 8; ++nt) {
                int nb = (wn * 64 + nt * 8 + r4) * S40 + kk + c2;
                uint2 q0 = *reinterpret_cast<const uint2*>(&sB[nb]);
                uint2 q1 = *reinterpret_cast<const uint2*>(&sB[nb + 8]);
                uint32_t bh[2], bl[2];
                bh[0] = __byte_perm(q0.x, q0.y, 0x7632);
                bl[0] = __byte_perm(q0.x, q0.y, 0x5410);
                bh[1] = __byte_perm(q1.x, q1.y, 0x7632);
                bl[1] = __byte_perm(q1.x, q1.y, 0x5410);
#pragma unroll
                for (int mt = 0; mt < 2; ++mt) {
                    mma_bf16(acc[mt][nt], ah[mt], bh);
                    mma_bf16(acc[mt][nt], al[mt], bh);
                    mma_bf16(acc[mt][nt], ah[mt], bl);
                }
            }
        }
        __syncthreads();
        if (c + 2 < NCH) issue(c + 2);
    }

    // ---- epilogue ----
    uint32_t* Cp = (csel == 1) ? g_h0p : g_h1p;
#pragma unroll
    for (int nt = 0; nt < 8; ++nt) {
        int col = bn + wn * 64 + nt * 8 + c2;
        float2 bv = *reinterpret_cast<const float2*>(bias + col);
#pragma unroll
        for (int mt = 0; mt < 2; ++mt) {
            int row0 = bm + wm * 32 + mt * 16 + r4;
            float2 o0, o1;
            o0.x = acc[mt][nt][0] + bv.x;
            o0.y = acc[mt][nt][1] + bv.y;
            o1.x = acc[mt][nt][2] + bv.x;
            o1.y = acc[mt][nt][3] + bv.y;
            if (relu) {
                o0.x = fmaxf(o0.x, 0.f); o0.y = fmaxf(o0.y, 0.f);
                o1.x = fmaxf(o1.x, 0.f); o1.y = fmaxf(o1.y, 0.f);
            }
            if (csel == 0) {
                if (row0 < NN)
                    *reinterpret_cast<float2*>(Cext + (size_t)row0 * 256 + col) = o0;
                if (row0 + 8 < NN)
                    *reinterpret_cast<float2*>(Cext + (size_t)(row0 + 8) * 256 + col) = o1;
            } else {
                if (row0 < NN) {
                    uint2 p = make_uint2(pack_split(o0.x), pack_split(o0.y));
                    *reinterpret_cast<uint2*>(Cp + (size_t)row0 * 256 + col) = p;
                }
                if (row0 + 8 < NN) {
                    uint2 p = make_uint2(pack_split(o1.x), pack_split(o1.y));
                    *reinterpret_cast<uint2*>(Cp + (size_t)(row0 + 8) * 256 + col) = p;
                }
            }
        }
    }
}

// ---------------------------------------------------------------------------
// launch: CSR build (stream B) overlapped with prep (stream A); then the
// serial fused per-layer schedule on stream A.  (R11 schedule)
// ---------------------------------------------------------------------------
extern "C" void kernel_launch(void* const* d_in, const int* in_sizes, int n_in,
                              void* d_out, int out_size) {
    const float* x    = (const float*)d_in[0];
    const float* W_l0 = (const float*)d_in[1];
    const float* b_l0 = (const float*)d_in[2];
    const float* W_r0 = (const float*)d_in[3];
    const float* W_l1 = (const float*)d_in[4];
    const float* b_l1 = (const float*)d_in[5];
    const float* W_r1 = (const float*)d_in[6];
    const float* W_l2 = (const float*)d_in[7];
    const float* b_l2 = (const float*)d_in[8];
    const float* W_r2 = (const float*)d_in[9];
    const int*   src  = (const int*)d_in[10];
    const int*   dst  = (const int*)d_in[11];
    float*       out  = (float*)d_out;

    const int T = 256;
    dim3 gg((NN + BM - 1) / BM, 256 / BN);

    static cudaStream_t sB = nullptr;
    static cudaEvent_t evFork, evCSR;
    if (!sB) {
        cudaStreamCreateWithFlags(&sB, cudaStreamNonBlocking);
        cudaEventCreateWithFlags(&evFork, cudaEventDisableTiming);
        cudaEventCreateWithFlags(&evCSR, cudaEventDisableTiming);
        cudaFuncSetAttribute(k_gemm_mma, cudaFuncAttributeMaxDynamicSharedMemorySize,
                             SMEM_BYTES);
    }

    // ---- fork: CSR build on stream B ----
    cudaEventRecord(evFork, 0);
    cudaStreamWaitEvent(sB, evFork, 0);
    k_zero_cnt<<<(NN + T - 1) / T, T, 0, sB>>>();
    k_hist<<<(NE / 4 + T - 1) / T, T, 0, sB>>>(dst);
    k_scan1<<<NB1, SCAN_B, 0, sB>>>();
    k_scan2<<<1, 256, 0, sB>>>();
    k_scan3<<<(NN + T - 1) / T, T, 0, sB>>>();
    k_place<<<(NE / 4 + T - 1) / T, T, 0, sB>>>(src, dst);
    cudaEventRecord(evCSR, sB);

    // ---- prep on stream A (overlaps CSR) ----
    k_prep_x<<<(NN * 128 + T - 1) / T, T>>>(x);
    k_prep_w_all<<<(WBUF_TOTAL + T - 1) / T, T>>>(W_l0, W_r0, W_l1, W_r1, W_l2, W_r2);

    // ---- join ----
    cudaStreamWaitEvent(0, evCSR, 0);

    // ---- layer 0 (K = 128) ----
    k_aggregate<1><<<(NN * 32 + T - 1) / T, T>>>(0);
    k_gemm_mma<<<gg, T, SMEM_BYTES>>>(0, 0, 32768, b_l0, nullptr, 1, 128, 1);

    // ---- layer 1 (K = 256) ----
    k_aggregate<2><<<(NN * 2 * 32 + T - 1) / T, T>>>(1);
    k_gemm_mma<<<gg, T, SMEM_BYTES>>>(1, 65536, 131072, b_l1, nullptr, 2, 256, 1);

    // ---- layer 2 (K = 256, no relu, write d_out) ----
    k_aggregate<2><<<(NN * 2 * 32 + T - 1) / T, T>>>(2);
    k_gemm_mma<<<gg, T, SMEM_BYTES>>>(2, 196608, 262144, b_l2, out, 0, 256, 0);
}